// round 3
// baseline (speedup 1.0000x reference)
#include <cuda_runtime.h>

#define NSER 8192
#define HALF 4096
#define OBS 9
#define LOG2PI_F 1.8378770664093453f

typedef unsigned long long u64;
struct F2 { u64 v; };

__device__ __forceinline__ F2 f2pack(float lo, float hi) {
    F2 r; asm("mov.b64 %0, {%1, %2};" : "=l"(r.v)
              : "r"(__float_as_uint(lo)), "r"(__float_as_uint(hi)));
    return r;
}
__device__ __forceinline__ F2 f2bc(float x) { return f2pack(x, x); }
__device__ __forceinline__ void f2unpack(F2 a, float& lo, float& hi) {
    unsigned l_, h_;
    asm("mov.b64 {%0, %1}, %2;" : "=r"(l_), "=r"(h_) : "l"(a.v));
    lo = __uint_as_float(l_); hi = __uint_as_float(h_);
}
__device__ __forceinline__ F2 operator*(F2 a, F2 b) {
    F2 r; asm("mul.rn.f32x2 %0, %1, %2;" : "=l"(r.v) : "l"(a.v), "l"(b.v)); return r;
}
__device__ __forceinline__ F2 operator+(F2 a, F2 b) {
    F2 r; asm("add.rn.f32x2 %0, %1, %2;" : "=l"(r.v) : "l"(a.v), "l"(b.v)); return r;
}
__device__ __forceinline__ F2 fm(F2 a, F2 b, F2 c) {   // a*b + c
    F2 r; asm("fma.rn.f32x2 %0, %1, %2, %3;" : "=l"(r.v)
              : "l"(a.v), "l"(b.v), "l"(c.v));
    return r;
}
__device__ __forceinline__ F2 operator-(F2 a, F2 b) {  // a - b  (= b*(-1)+a)
    F2 r; const u64 n1 = 0xBF800000BF800000ULL;
    asm("fma.rn.f32x2 %0, %1, %2, %3;" : "=l"(r.v) : "l"(b.v), "l"(n1), "l"(a.v));
    return r;
}
__device__ __forceinline__ F2 f2neg(F2 a) {
    F2 r; const u64 n1 = 0xBF800000BF800000ULL;
    asm("mul.rn.f32x2 %0, %1, %2;" : "=l"(r.v) : "l"(a.v), "l"(n1)); return r;
}
__device__ __forceinline__ F2 f2rcp(F2 a) {
    float lo, hi; f2unpack(a, lo, hi);
    float rl, rh;
    asm("rcp.approx.ftz.f32 %0, %1;" : "=f"(rl) : "f"(lo));
    asm("rcp.approx.ftz.f32 %0, %1;" : "=f"(rh) : "f"(hi));
    return f2pack(rl, rh);
}
__device__ __forceinline__ F2 f2exp(F2 a) {
    float lo, hi; f2unpack(a, lo, hi);
    return f2pack(__expf(lo), __expf(hi));
}
__device__ __forceinline__ F2 f2log(F2 a) {
    float lo, hi; f2unpack(a, lo, hi);
    return f2pack(__logf(lo), __logf(hi));
}

static __device__ double g_partials[128];

__global__ void __launch_bounds__(32) kf_kernel(
    const float* __restrict__ y,
    const float* __restrict__ B1s1_p,
    const float* __restrict__ B1s2_p,
    const float* __restrict__ lam1_p,
    const float* __restrict__ lam2_p,
    const float* __restrict__ logq_p,
    const float* __restrict__ logr_p,
    const float* __restrict__ gami_p,
    const float* __restrict__ gamc_p,
    int NT)
{
    const int n = blockIdx.x * 32 + threadIdx.x;       // 0..4095
    const float* ypA = y + (size_t)n * NT * OBS;
    const float* ypB = y + (size_t)(n + HALF) * NT * OBS;

    // ---------------- packed constants ----------------
    F2 B[3][3];
#pragma unroll
    for (int i = 0; i < 3; ++i)
#pragma unroll
        for (int j = 0; j < 3; ++j)
            B[i][j] = f2bc(B1s1_p[i * 3 + j]);
    const F2 b3 = f2bc(B1s2_p[0]);

    F2 q[4];
#pragma unroll
    for (int l = 0; l < 4; ++l) q[l] = f2bc(expf(logq_p[l]));

    float c1s[9], c2s[9];
    c1s[0] = 1.f; c1s[1] = lam1_p[0]; c1s[2] = lam1_p[1];
    c1s[3] = 1.f; c1s[4] = lam1_p[2]; c1s[5] = lam1_p[3];
    c1s[6] = 1.f; c1s[7] = lam1_p[4]; c1s[8] = lam1_p[5];
    c2s[0] = 1.f;
#pragma unroll
    for (int o = 1; o < 9; ++o) c2s[o] = lam2_p[o - 1];

    float logdetD = 0.f;
    float a1s[3] = {0.f, 0.f, 0.f};
    float a2s = 0.f;
    F2 dinv[9], nc1[9], nc2[9];
#pragma unroll
    for (int o = 0; o < 9; ++o) {
        float r = expf(logr_p[o]);
        float d = r + 1e-6f;
        float di = 1.f / d;
        dinv[o] = f2bc(di);
        nc1[o] = f2bc(-c1s[o]);
        nc2[o] = f2bc(-c2s[o]);
        logdetD += logf(d);
        a1s[o / 3] += c1s[o] * c1s[o] * di;
        a2s += c2s[o] * c2s[o] * di;
    }
    F2 a1[3], na1[3];
#pragma unroll
    for (int k = 0; k < 3; ++k) { a1[k] = f2bc(a1s[k]); na1[k] = f2bc(-a1s[k]); }
    const F2 a2 = f2bc(a2s), na2 = f2bc(-a2s);
    const F2 CK = f2bc(-0.5f * (9.f * LOG2PI_F + logdetD));
    const F2 MHALF = f2bc(-0.5f);
    const F2 ONE = f2bc(1.f);
    const F2 Z = f2bc(0.f);
    const F2 EPS9 = f2bc(1e-9f);
    const F2 g0 = f2bc(gami_p[0]);
    const F2 gc0 = f2bc(gamc_p[0]), gc1 = f2bc(gamc_p[1]), gc2 = f2bc(gamc_p[2]);

    // ---------------- packed state (2 series per thread) ----------------
    F2 P[4][4];
#pragma unroll
    for (int i = 0; i < 4; ++i)
#pragma unroll
        for (int j = 0; j < 4; ++j)
            P[i][j] = f2bc((i == j) ? 1000.f : 0.f);
    F2 eta[4] = {Z, Z, Z, Z};
    F2 p1v = f2bc(0.99f), p2v = f2bc(0.01f);
    F2 llacc = Z;

    F2 yc[9];
#pragma unroll
    for (int o = 0; o < 9; ++o) yc[o] = f2pack(ypA[o], ypB[o]);

#pragma unroll 1
    for (int t = 0; t < NT; ++t) {
        // ---- prefetch next step's observations (both series) ----
        F2 yn[9];
        {
            const float* ap = ypA + (t + 1) * OBS;
            const float* bp = ypB + (t + 1) * OBS;
            const bool have = (t + 1) < NT;
#pragma unroll
            for (int o = 0; o < 9; ++o) {
                float av = have ? ap[o] : 0.f;
                float bv = have ? bp[o] : 0.f;
                yn[o] = f2pack(av, bv);
            }
        }

        // ---- transition prob ----
        F2 lg = fm(gc0, eta[0], fm(gc1, eta[1], fm(gc2, eta[2], g0)));
        F2 p11 = f2rcp(ONE + f2exp(f2neg(lg)));
        F2 p12 = ONE - p11;

        // ---- predict ----
        F2 ep[4];
        ep[0] = fm(B[0][0], eta[0], fm(B[0][1], eta[1], B[0][2] * eta[2]));
        ep[1] = fm(B[1][0], eta[0], fm(B[1][1], eta[1], B[1][2] * eta[2]));
        ep[2] = fm(B[2][0], eta[0], fm(B[2][1], eta[1], B[2][2] * eta[2]));
        ep[3] = b3 * eta[3];

        F2 T[4][4];
#pragma unroll
        for (int i = 0; i < 3; ++i)
#pragma unroll
            for (int j = 0; j < 4; ++j)
                T[i][j] = fm(B[i][0], P[0][j], fm(B[i][1], P[1][j], B[i][2] * P[2][j]));
#pragma unroll
        for (int j = 0; j < 4; ++j) T[3][j] = b3 * P[3][j];

        F2 Pp[4][4];
#pragma unroll
        for (int i = 0; i < 4; ++i) {
#pragma unroll
            for (int j = i; j < 4; ++j) {
                F2 v = (j < 3)
                     ? fm(T[i][0], B[j][0], fm(T[i][1], B[j][1], T[i][2] * B[j][2]))
                     : T[i][3] * b3;
                Pp[i][j] = v; Pp[j][i] = v;
            }
        }
        Pp[0][0] = Pp[0][0] + q[0]; Pp[1][1] = Pp[1][1] + q[1];
        Pp[2][2] = Pp[2][2] + q[2]; Pp[3][3] = Pp[3][3] + q[3];

        // ================= Regime 1: single-inverse Woodbury =================
        // S = I + M*diag(a1);  W = S^-1 M;  logdet F1 = logdetD + log det S
        F2 m00 = Pp[0][0], m01 = Pp[0][1], m02 = Pp[0][2];
        F2 m11 = Pp[1][1], m12 = Pp[1][2], m22 = Pp[2][2];
        F2 S00 = fm(m00, a1[0], ONE), S01 = m01 * a1[1], S02 = m02 * a1[2];
        F2 S10 = m01 * a1[0], S11 = fm(m11, a1[1], ONE), S12 = m12 * a1[2];
        F2 S20 = m02 * a1[0], S21 = m12 * a1[1], S22 = fm(m22, a1[2], ONE);

        F2 adj00 = S11 * S22 - S12 * S21;
        F2 adj01 = S02 * S21 - S01 * S22;
        F2 adj02 = S01 * S12 - S02 * S11;
        F2 adj10 = S12 * S20 - S10 * S22;
        F2 adj11 = S00 * S22 - S02 * S20;
        F2 adj12 = S02 * S10 - S00 * S12;
        F2 adj20 = S10 * S21 - S11 * S20;
        F2 adj21 = S01 * S20 - S00 * S21;
        F2 adj22 = S00 * S11 - S01 * S10;
        F2 detS = fm(S00, adj00, fm(S01, adj10, S02 * adj20));
        F2 idS = f2rcp(detS);

        F2 W00 = idS * fm(adj00, m00, fm(adj01, m01, adj02 * m02));
        F2 W01 = idS * fm(adj00, m01, fm(adj01, m11, adj02 * m12));
        F2 W02 = idS * fm(adj00, m02, fm(adj01, m12, adj02 * m22));
        F2 W11 = idS * fm(adj10, m01, fm(adj11, m11, adj12 * m12));
        F2 W12 = idS * fm(adj10, m02, fm(adj11, m12, adj12 * m22));
        F2 W22 = idS * fm(adj20, m02, fm(adj21, m12, adj22 * m22));

        // innovation (mu = -u)
        F2 mu0 = Z, mu1 = Z, mu2 = Z, quadD = Z;
#pragma unroll
        for (int o = 0; o < 9; ++o) {
            F2 v = fm(nc1[o], ep[o / 3], yc[o]);
            F2 sv = v * dinv[o];
            quadD = fm(v, sv, quadD);
            if (o < 3) mu0 = fm(nc1[o], sv, mu0);
            else if (o < 6) mu1 = fm(nc1[o], sv, mu1);
            else mu2 = fm(nc1[o], sv, mu2);
        }
        F2 wu0 = fm(W00, mu0, fm(W01, mu1, W02 * mu2));
        F2 wu1 = fm(W01, mu0, fm(W11, mu1, W12 * mu2));
        F2 wu2 = fm(W02, mu0, fm(W12, mu1, W22 * mu2));
        F2 uw = fm(mu0, wu0, fm(mu1, wu1, mu2 * wu2));   // = u^T W u
        F2 quad1 = quadD - uw;
        F2 lp1 = fm(MHALF, quad1 + f2log(detS), CK);

        F2 u0 = f2neg(mu0), u1 = f2neg(mu1), u2 = f2neg(mu2);

        // V = -diag(a1) W ;  K1s = Pp[:,:3] (I + V)
        F2 V00 = na1[0] * W00, V01 = na1[0] * W01, V02 = na1[0] * W02;
        F2 V10 = na1[1] * W01, V11 = na1[1] * W11, V12 = na1[1] * W12;
        F2 V20 = na1[2] * W02, V21 = na1[2] * W12, V22 = na1[2] * W22;

        F2 K1s[4][3], nKa[4][3];
#pragma unroll
        for (int l = 0; l < 4; ++l) {
            K1s[l][0] = fm(Pp[l][0], V00, fm(Pp[l][1], V10, fm(Pp[l][2], V20, Pp[l][0])));
            K1s[l][1] = fm(Pp[l][0], V01, fm(Pp[l][1], V11, fm(Pp[l][2], V21, Pp[l][1])));
            K1s[l][2] = fm(Pp[l][0], V02, fm(Pp[l][1], V12, fm(Pp[l][2], V22, Pp[l][2])));
            nKa[l][0] = K1s[l][0] * na1[0];
            nKa[l][1] = K1s[l][1] * na1[1];
            nKa[l][2] = K1s[l][2] * na1[2];
        }
        F2 eta1[4];
#pragma unroll
        for (int l = 0; l < 4; ++l)
            eta1[l] = fm(K1s[l][0], u0, fm(K1s[l][1], u1, fm(K1s[l][2], u2, ep[l])));

        F2 P1u[10];
        {
            int idx = 0;
#pragma unroll
            for (int l = 0; l < 4; ++l)
#pragma unroll
                for (int j = 0; j < 4; ++j)
                    if (j >= l)
                        P1u[idx++] = fm(nKa[l][0], Pp[0][j],
                                     fm(nKa[l][1], Pp[1][j],
                                     fm(nKa[l][2], Pp[2][j], Pp[l][j])));
        }

        // ================= Regime 2: rank-1 Sherman-Morrison =================
        F2 s = Pp[3][3];
        F2 den = fm(s, a2, ONE);
        F2 iden = f2rcp(den);
        F2 k2[4], nk2a[4];
#pragma unroll
        for (int l = 0; l < 4; ++l) {
            k2[l] = Pp[l][3] * iden;
            nk2a[l] = k2[l] * na2;
        }
        F2 mus = Z, quadD2 = Z;
#pragma unroll
        for (int o = 0; o < 9; ++o) {
            F2 v = fm(nc2[o], ep[3], yc[o]);
            F2 sv = v * dinv[o];
            quadD2 = fm(v, sv, quadD2);
            mus = fm(nc2[o], sv, mus);
        }
        F2 u2s = f2neg(mus);
        F2 quad2 = quadD2 - (s * (mus * mus)) * iden;
        F2 lp2 = fm(MHALF, quad2 + f2log(den), CK);

        F2 eta2[4];
#pragma unroll
        for (int l = 0; l < 4; ++l) eta2[l] = fm(k2[l], u2s, ep[l]);

        F2 P2u[10];
        {
            int idx = 0;
#pragma unroll
            for (int l = 0; l < 4; ++l)
#pragma unroll
                for (int j = 0; j < 4; ++j)
                    if (j >= l)
                        P2u[idx++] = fm(nk2a[l], Pp[3][j], Pp[l][j]);
        }

        // ================= mixture collapse =================
        F2 lik1 = f2exp(lp1);
        F2 lik2 = f2exp(lp2);
        F2 num1 = lik1 * (p1v * p11);             // p21 = 0
        F2 num2 = lik2 * fm(p1v, p12, p2v);       // p22 = 1
        F2 marg = num1 + num2 + EPS9;
        F2 im = f2rcp(marg);
        F2 pt1 = num1 * im, pt2 = num2 * im;
        llacc = llacc + f2log(marg);

        F2 dd1[4], dd2[4];
#pragma unroll
        for (int l = 0; l < 4; ++l) {
            F2 e = fm(pt1, eta1[l], pt2 * eta2[l]);
            dd1[l] = eta1[l] - e;
            dd2[l] = eta2[l] - e;
            eta[l] = e;
        }
        {
            int idx = 0;
#pragma unroll
            for (int l = 0; l < 4; ++l)
#pragma unroll
                for (int j = 0; j < 4; ++j)
                    if (j >= l) {
                        F2 t1 = fm(dd1[l], dd1[j], P1u[idx]);
                        F2 t2 = fm(dd2[l], dd2[j], P2u[idx]);
                        F2 pn = fm(pt1, t1, pt2 * t2);
                        P[l][j] = pn; P[j][l] = pn;
                        ++idx;
                    }
        }
        p1v = pt1; p2v = pt2;
#pragma unroll
        for (int o = 0; o < 9; ++o) yc[o] = yn[o];
    }

    // ---- deterministic reduction ----
    float llo, llh;
    f2unpack(llacc, llo, llh);
    double v = (double)llo + (double)llh;
#pragma unroll
    for (int off = 16; off > 0; off >>= 1)
        v += __shfl_down_sync(0xffffffffu, v, off);
    if (threadIdx.x == 0) g_partials[blockIdx.x] = v;
}

__global__ void reduce_kernel(float* out)
{
    __shared__ double sh[128];
    const int t = threadIdx.x;
    sh[t] = g_partials[t];
    __syncthreads();
    for (int k = 64; k > 0; k >>= 1) {
        if (t < k) sh[t] += sh[t + k];
        __syncthreads();
    }
    if (t == 0) out[0] = (float)(-sh[0]);
}

extern "C" void kernel_launch(void* const* d_in, const int* in_sizes, int n_in,
                              void* d_out, int out_size)
{
    const float* y    = (const float*)d_in[0];
    const float* B1s1 = (const float*)d_in[1];
    const float* B1s2 = (const float*)d_in[2];
    const float* lam1 = (const float*)d_in[3];
    const float* lam2 = (const float*)d_in[4];
    const float* logq = (const float*)d_in[5];
    const float* logr = (const float*)d_in[6];
    const float* gami = (const float*)d_in[7];
    const float* gamc = (const float*)d_in[8];

    const int NT = in_sizes[0] / (NSER * OBS);   // 400

    kf_kernel<<<HALF / 32, 32>>>(y, B1s1, B1s2, lam1, lam2, logq, logr, gami, gamc, NT);
    reduce_kernel<<<1, 128>>>((float*)d_out);
}

// round 4
// speedup vs baseline: 1.8505x; 1.8505x over previous
#include <cuda_runtime.h>

#define NSER 8192
#define OBS 9
#define NBLK 128
#define TPB 64
#define LOG2PI_F 1.8378770664093453f

static __device__ double g_partials[NBLK];

// 128 CTAs x 64 threads: <=1 CTA per SM, so each CTA's 2 warps sit on distinct
// SMSPs -> 256 warps on 256 distinct SMSPs, no FMA-pipe sharing.
__global__ void __launch_bounds__(TPB) kf_kernel(
    const float* __restrict__ y,
    const float* __restrict__ B1s1_p,
    const float* __restrict__ B1s2_p,
    const float* __restrict__ lam1_p,
    const float* __restrict__ lam2_p,
    const float* __restrict__ logq_p,
    const float* __restrict__ logr_p,
    const float* __restrict__ gami_p,
    const float* __restrict__ gamc_p,
    int NT)
{
    const int n = blockIdx.x * TPB + threadIdx.x;

    // ---------------- constants ----------------
    float B[3][3];
#pragma unroll
    for (int i = 0; i < 3; ++i)
#pragma unroll
        for (int j = 0; j < 3; ++j)
            B[i][j] = B1s1_p[i * 3 + j];
    const float b3 = B1s2_p[0];

    float q[4];
#pragma unroll
    for (int l = 0; l < 4; ++l) q[l] = expf(logq_p[l]);

    float c1[9], c2[9], dinv[9];
    c1[0] = 1.f; c1[1] = lam1_p[0]; c1[2] = lam1_p[1];
    c1[3] = 1.f; c1[4] = lam1_p[2]; c1[5] = lam1_p[3];
    c1[6] = 1.f; c1[7] = lam1_p[4]; c1[8] = lam1_p[5];
    c2[0] = 1.f;
#pragma unroll
    for (int o = 1; o < 9; ++o) c2[o] = lam2_p[o - 1];

    float logdetD = 0.f;
    float a1[3] = {0.f, 0.f, 0.f};
    float a2 = 0.f;
#pragma unroll
    for (int o = 0; o < 9; ++o) {
        float r = expf(logr_p[o]);
        float d = r + 1e-6f;
        float di = 1.f / d;
        dinv[o] = di;
        logdetD += logf(d);
        a1[o / 3] += c1[o] * c1[o] * di;   // U^T D^-1 U (diag, disjoint support)
        a2 += c2[o] * c2[o] * di;
    }
    const float CK = -0.5f * (9.f * LOG2PI_F + logdetD);   // constant part of logprob
    const float g0 = gami_p[0];
    const float gc0 = gamc_p[0], gc1 = gamc_p[1], gc2 = gamc_p[2];

    // ---------------- state ----------------
    float P[4][4];
#pragma unroll
    for (int i = 0; i < 4; ++i)
#pragma unroll
        for (int j = 0; j < 4; ++j)
            P[i][j] = (i == j) ? 1000.f : 0.f;
    float eta[4] = {0.f, 0.f, 0.f, 0.f};
    float p1 = 0.99f, p2 = 0.01f;
    double ll = 0.0;

    const float* yp = y + (size_t)n * NT * OBS;
    float yc[9];
#pragma unroll
    for (int o = 0; o < 9; ++o) yc[o] = yp[o];

#pragma unroll 1
    for (int t = 0; t < NT; ++t) {
        // ---- prefetch next step's observations (MLP=9, hides DRAM latency) ----
        float yn[9];
        {
            const float* ynp = yp + (t + 1) * OBS;
            const bool have = (t + 1) < NT;
#pragma unroll
            for (int o = 0; o < 9; ++o) yn[o] = have ? ynp[o] : 0.f;
        }

        // ---- transition prob (pre-update eta) ----
        float lg = g0 + gc0 * eta[0] + gc1 * eta[1] + gc2 * eta[2];
        float p11 = __fdividef(1.f, 1.f + __expf(-lg));
        float p12 = 1.f - p11;

        // ---- predict ----
        float ep[4];
        ep[0] = B[0][0] * eta[0] + B[0][1] * eta[1] + B[0][2] * eta[2];
        ep[1] = B[1][0] * eta[0] + B[1][1] * eta[1] + B[1][2] * eta[2];
        ep[2] = B[2][0] * eta[0] + B[2][1] * eta[1] + B[2][2] * eta[2];
        ep[3] = b3 * eta[3];

        float T[4][4];
#pragma unroll
        for (int i = 0; i < 3; ++i)
#pragma unroll
            for (int j = 0; j < 4; ++j)
                T[i][j] = B[i][0] * P[0][j] + B[i][1] * P[1][j] + B[i][2] * P[2][j];
#pragma unroll
        for (int j = 0; j < 4; ++j) T[3][j] = b3 * P[3][j];

        float Pp[4][4];
#pragma unroll
        for (int i = 0; i < 4; ++i) {
#pragma unroll
            for (int j = i; j < 4; ++j) {
                float v = (j < 3)
                        ? T[i][0] * B[j][0] + T[i][1] * B[j][1] + T[i][2] * B[j][2]
                        : T[i][3] * b3;
                Pp[i][j] = v; Pp[j][i] = v;
            }
        }
        Pp[0][0] += q[0]; Pp[1][1] += q[1]; Pp[2][2] += q[2]; Pp[3][3] += q[3];

        // ================= Regime 1: single-inverse Woodbury =================
        // S = I + M*diag(a1);  W = S^-1 M = (M^-1 + diag(a1))^-1 (symmetric);
        // logdet F1 = logdetD + log det S
        float m00 = Pp[0][0], m01 = Pp[0][1], m02 = Pp[0][2];
        float m11 = Pp[1][1], m12 = Pp[1][2], m22 = Pp[2][2];
        float S00 = 1.f + m00 * a1[0], S01 = m01 * a1[1], S02 = m02 * a1[2];
        float S10 = m01 * a1[0], S11 = 1.f + m11 * a1[1], S12 = m12 * a1[2];
        float S20 = m02 * a1[0], S21 = m12 * a1[1], S22 = 1.f + m22 * a1[2];

        float adj00 = S11 * S22 - S12 * S21;
        float adj01 = S02 * S21 - S01 * S22;
        float adj02 = S01 * S12 - S02 * S11;
        float adj10 = S12 * S20 - S10 * S22;
        float adj11 = S00 * S22 - S02 * S20;
        float adj12 = S02 * S10 - S00 * S12;
        float adj20 = S10 * S21 - S11 * S20;
        float adj21 = S01 * S20 - S00 * S21;
        float adj22 = S00 * S11 - S01 * S10;
        float detS = S00 * adj00 + S01 * adj10 + S02 * adj20;
        float idS = __fdividef(1.f, detS);

        float W00 = idS * (adj00 * m00 + adj01 * m01 + adj02 * m02);
        float W01 = idS * (adj00 * m01 + adj01 * m11 + adj02 * m12);
        float W02 = idS * (adj00 * m02 + adj01 * m12 + adj02 * m22);
        float W11 = idS * (adj10 * m01 + adj11 * m11 + adj12 * m12);
        float W12 = idS * (adj10 * m02 + adj11 * m12 + adj12 * m22);
        float W22 = idS * (adj20 * m02 + adj21 * m12 + adj22 * m22);

        // innovation, u = U^T D^-1 v, quadD = v^T D^-1 v
        float u0 = 0.f, u1 = 0.f, u2v = 0.f, quadD = 0.f;
#pragma unroll
        for (int o = 0; o < 9; ++o) {
            float v = yc[o] - c1[o] * ep[o / 3];
            float sv = v * dinv[o];
            quadD += v * sv;
            float csv = c1[o] * sv;
            if (o < 3) u0 += csv; else if (o < 6) u1 += csv; else u2v += csv;
        }
        float quad1 = quadD - (u0 * (W00 * u0 + W01 * u1 + W02 * u2v)
                             + u1 * (W01 * u0 + W11 * u1 + W12 * u2v)
                             + u2v * (W02 * u0 + W12 * u1 + W22 * u2v));
        float lp1 = -0.5f * (quad1 + __logf(detS)) + CK;

        // G = I - diag(a1) W (row-scaled); K1s = Pp[:,0:3] G
        float G00 = 1.f - a1[0] * W00, G01 = -a1[0] * W01, G02 = -a1[0] * W02;
        float G10 = -a1[1] * W01, G11 = 1.f - a1[1] * W11, G12 = -a1[1] * W12;
        float G20 = -a1[2] * W02, G21 = -a1[2] * W12, G22 = 1.f - a1[2] * W22;

        float K1s[4][3], Ka[4][3];
#pragma unroll
        for (int l = 0; l < 4; ++l) {
            K1s[l][0] = Pp[l][0] * G00 + Pp[l][1] * G10 + Pp[l][2] * G20;
            K1s[l][1] = Pp[l][0] * G01 + Pp[l][1] * G11 + Pp[l][2] * G21;
            K1s[l][2] = Pp[l][0] * G02 + Pp[l][1] * G12 + Pp[l][2] * G22;
            Ka[l][0] = K1s[l][0] * a1[0];
            Ka[l][1] = K1s[l][1] * a1[1];
            Ka[l][2] = K1s[l][2] * a1[2];
        }
        float eta1[4];
#pragma unroll
        for (int l = 0; l < 4; ++l)
            eta1[l] = ep[l] + K1s[l][0] * u0 + K1s[l][1] * u1 + K1s[l][2] * u2v;

        // short-form P1 = (I - K1 L1) Pp (Joseph delta = 1e-6*K K^T, negligible)
        float P1u[10];
        {
            int idx = 0;
#pragma unroll
            for (int l = 0; l < 4; ++l)
#pragma unroll
                for (int j = 0; j < 4; ++j)
                    if (j >= l)
                        P1u[idx++] = Pp[l][j] - Ka[l][0] * Pp[0][j]
                                              - Ka[l][1] * Pp[1][j]
                                              - Ka[l][2] * Pp[2][j];
        }

        // ================= Regime 2: rank-1 Sherman-Morrison =================
        float s = Pp[3][3];
        float denom = 1.f + s * a2;
        float iden = __fdividef(1.f, denom);
        float k2[4], ak[4];
#pragma unroll
        for (int l = 0; l < 4; ++l) { k2[l] = Pp[l][3] * iden; ak[l] = a2 * k2[l]; }

        float u2s = 0.f, quadD2 = 0.f;
#pragma unroll
        for (int o = 0; o < 9; ++o) {
            float v = yc[o] - c2[o] * ep[3];
            float sv = v * dinv[o];
            quadD2 += v * sv;
            u2s += c2[o] * sv;
        }
        float quad2 = quadD2 - s * u2s * u2s * iden;
        float lp2 = -0.5f * (quad2 + __logf(denom)) + CK;

        float eta2[4];
#pragma unroll
        for (int l = 0; l < 4; ++l) eta2[l] = ep[l] + k2[l] * u2s;

        float P2u[10];
        {
            int idx = 0;
#pragma unroll
            for (int l = 0; l < 4; ++l)
#pragma unroll
                for (int j = 0; j < 4; ++j)
                    if (j >= l)
                        P2u[idx++] = Pp[l][j] - ak[l] * Pp[3][j];
        }

        // ================= mixture collapse =================
        float lik1 = __expf(lp1);
        float lik2 = __expf(lp2);
        float num1 = lik1 * (p1 * p11);            // p21 = 0
        float num2 = lik2 * (p1 * p12 + p2);       // p22 = 1
        float marg = num1 + num2 + 1e-9f;
        float im = __fdividef(1.f, marg);
        float pt1 = num1 * im, pt2 = num2 * im;
        ll += (double)__logf(marg);

        float dd1[4], dd2[4];
#pragma unroll
        for (int l = 0; l < 4; ++l) {
            float e = pt1 * eta1[l] + pt2 * eta2[l];
            dd1[l] = eta1[l] - e;
            dd2[l] = eta2[l] - e;
            eta[l] = e;
        }
        {
            int idx = 0;
#pragma unroll
            for (int l = 0; l < 4; ++l)
#pragma unroll
                for (int j = 0; j < 4; ++j)
                    if (j >= l) {
                        float pn = pt1 * (P1u[idx] + dd1[l] * dd1[j])
                                 + pt2 * (P2u[idx] + dd2[l] * dd2[j]);
                        P[l][j] = pn; P[j][l] = pn;
                        ++idx;
                    }
        }
        p1 = pt1; p2 = pt2;
#pragma unroll
        for (int o = 0; o < 9; ++o) yc[o] = yn[o];
    }

    // ---- deterministic reduction: warp shuffle, then cross-warp via smem ----
    double v = ll;
#pragma unroll
    for (int off = 16; off > 0; off >>= 1)
        v += __shfl_down_sync(0xffffffffu, v, off);

    __shared__ double wsum[TPB / 32];
    if ((threadIdx.x & 31) == 0) wsum[threadIdx.x >> 5] = v;
    __syncthreads();
    if (threadIdx.x == 0) {
        double s = wsum[0];
#pragma unroll
        for (int w = 1; w < TPB / 32; ++w) s += wsum[w];
        g_partials[blockIdx.x] = s;
    }
}

__global__ void reduce_kernel(float* out)
{
    __shared__ double sh[NBLK];
    const int t = threadIdx.x;
    sh[t] = g_partials[t];
    __syncthreads();
    for (int k = NBLK / 2; k > 0; k >>= 1) {
        if (t < k) sh[t] += sh[t + k];
        __syncthreads();
    }
    if (t == 0) out[0] = (float)(-sh[0]);
}

extern "C" void kernel_launch(void* const* d_in, const int* in_sizes, int n_in,
                              void* d_out, int out_size)
{
    const float* y    = (const float*)d_in[0];
    const float* B1s1 = (const float*)d_in[1];
    const float* B1s2 = (const float*)d_in[2];
    const float* lam1 = (const float*)d_in[3];
    const float* lam2 = (const float*)d_in[4];
    const float* logq = (const float*)d_in[5];
    const float* logr = (const float*)d_in[6];
    const float* gami = (const float*)d_in[7];
    const float* gamc = (const float*)d_in[8];

    const int NT = in_sizes[0] / (NSER * OBS);   // 400

    kf_kernel<<<NBLK, TPB>>>(y, B1s1, B1s2, lam1, lam2, logq, logr, gami, gamc, NT);
    reduce_kernel<<<1, NBLK>>>((float*)d_out);
}